// round 7
// baseline (speedup 1.0000x reference)
#include <cuda_runtime.h>
#include <cstdint>

#define MAXN 100000
#define MAXE 1250000
#define DH   64
#define CC   40

// ---------------- device scratch (static; no runtime allocation) -------------
__device__ __align__(16) float g_dis[MAXN];
__device__ int   g_deg[MAXN];
__device__ int   g_rowptr[MAXN + 1];
__device__ int   g_cur[MAXN];
__device__ int   g_csr[MAXE];
__device__ volatile unsigned long long g_pack[512];   // lookback scan state
__device__ int   g_is64;
__device__ __align__(16) float g_h1[(size_t)MAXN * DH];   // hop-1 activation

// ---------------- helpers ----------------------------------------------------
__device__ __forceinline__ int edge_at(const void* ei, long long pos) {
    if (g_is64) return (int)((const long long*)ei)[pos];
    return ((const int*)ei)[pos];
}

// zero deg + scan state + int64/int32 detection, one kernel
__global__ void k_init(const void* ei, int n) {
    int i = blockIdx.x * blockDim.x + threadIdx.x;
    if (i < n) g_deg[i] = 0;
    if (i < 512) g_pack[i] = 0ull;
    if (i == 0) {
        const long long* p = (const long long*)ei;
        int ok = 1;
        #pragma unroll
        for (int k = 0; k < 8; k++) {
            long long v = p[k];
            if (v < 0 || v >= (long long)n) ok = 0;
        }
        g_is64 = ok;
    }
}

__global__ void k_count(const void* ei, int E) {
    int e = blockIdx.x * blockDim.x + threadIdx.x;
    if (e < E) atomicAdd(&g_deg[edge_at(ei, (long long)E + e)], 1);
}

// ---- single-pass exclusive scan (decoupled lookback) -> rowptr/cur/dis ------
#define FLAG_AGG (1ull << 62)
#define FLAG_PRE (2ull << 62)

__global__ void k_scan(int n) {
    __shared__ int s[256];
    __shared__ int s_prefix;
    const int b = blockIdx.x;
    const int t = threadIdx.x;
    const int i = b * 256 + t;
    const int v = (i < n) ? g_deg[i] : 0;

    s[t] = v;
    __syncthreads();
    #pragma unroll
    for (int off = 1; off < 256; off <<= 1) {
        int add = (t >= off) ? s[t - off] : 0;
        __syncthreads();
        s[t] += add;
        __syncthreads();
    }
    // s[t] = inclusive prefix within block; s[255] = block total

    if (t == 0) {
        int total = s[255];
        if (b == 0) {
            g_pack[0] = FLAG_PRE | (unsigned long long)(unsigned)total;
            s_prefix = 0;
        } else {
            g_pack[b] = FLAG_AGG | (unsigned long long)(unsigned)total;
            int prefix = 0;
            int j = b - 1;
            while (true) {
                unsigned long long p;
                while ((p = g_pack[j]) == 0ull) { /* spin */ }
                int val = (int)(p & 0xFFFFFFFFull);
                prefix += val;
                if (p & FLAG_PRE) break;
                j--;
            }
            g_pack[b] = FLAG_PRE | (unsigned long long)(unsigned)(prefix + total);
            s_prefix = prefix;
        }
    }
    __syncthreads();

    if (i < n) {
        int excl = s_prefix + s[t] - v;
        g_rowptr[i] = excl;
        g_cur[i]    = excl;
        g_dis[i]    = rsqrtf((float)(v + 1));     // +1 = self-loop
        if (i == n - 1) g_rowptr[n] = excl + v;
    }
}

__global__ void k_fill(const void* ei, int E) {
    int e = blockIdx.x * blockDim.x + threadIdx.x;
    if (e < E) {
        int r = edge_at(ei, (long long)e);
        int c = edge_at(ei, (long long)E + e);
        int pos = atomicAdd(&g_cur[c], 1);
        g_csr[pos] = r;
    }
}

// ---- shared building block: aggregate 64 rows of S into smem tile Xs --------
// Xs row stride 68 floats. warp-per-node, lane owns float2.
// y_i = dis_i*S_i + sum_{r->i} dis_r*S_r
__device__ __forceinline__ void agg_tile(float* Xs, const float* __restrict__ S,
                                         int r0, int n, int tid)
{
    const float2* H = (const float2*)S;
    const int w = tid >> 5, lane = tid & 31;
    #pragma unroll
    for (int i = 0; i < 8; i++) {
        const int node = r0 + w * 8 + i;
        float2 acc = make_float2(0.f, 0.f);
        if (node < n) {
            float  dw = g_dis[node];
            float2 v0 = H[(size_t)node * 32 + lane];
            acc.x = dw * v0.x;
            acc.y = dw * v0.y;
            int p   = g_rowptr[node];
            int end = g_rowptr[node + 1];
            for (; p + 3 < end; p += 4) {
                int s0 = __ldg(&g_csr[p]);
                int s1 = __ldg(&g_csr[p + 1]);
                int s2 = __ldg(&g_csr[p + 2]);
                int s3 = __ldg(&g_csr[p + 3]);
                float d0 = __ldg(&g_dis[s0]);
                float d1 = __ldg(&g_dis[s1]);
                float d2 = __ldg(&g_dis[s2]);
                float d3 = __ldg(&g_dis[s3]);
                float2 a = H[(size_t)s0 * 32 + lane];
                float2 b = H[(size_t)s1 * 32 + lane];
                float2 c = H[(size_t)s2 * 32 + lane];
                float2 d = H[(size_t)s3 * 32 + lane];
                acc.x = fmaf(d0, a.x, fmaf(d1, b.x, fmaf(d2, c.x, fmaf(d3, d.x, acc.x))));
                acc.y = fmaf(d0, a.y, fmaf(d1, b.y, fmaf(d2, c.y, fmaf(d3, d.y, acc.y))));
            }
            for (; p < end; p++) {
                int s0 = __ldg(&g_csr[p]);
                float d0 = __ldg(&g_dis[s0]);
                float2 a = H[(size_t)s0 * 32 + lane];
                acc.x = fmaf(d0, a.x, acc.x);
                acc.y = fmaf(d0, a.y, acc.y);
            }
        }
        *(float2*)&Xs[(w * 8 + i) * 68 + lane * 2] = acc;
    }
}

// ------------- hop 1 fused: h1 = relu(dis * (agg(x) @ W0) + b0) --------------
// block (16,16), 64-row tile: CSR-aggregate x into smem, then GEMM.
__global__ void k_hop1(const float* __restrict__ x, const float* __restrict__ W,
                       const float* __restrict__ bias, float* __restrict__ out, int n)
{
    __shared__ float  Xs[64 * 68];     // aggregated tile, stride 68
    __shared__ float4 Ws[64 * 16];

    const int tx = threadIdx.x, ty = threadIdx.y;
    const int tid = ty * 16 + tx;
    const int r0 = blockIdx.x * 64;

    const float4* Wv = (const float4*)W;
    #pragma unroll
    for (int i = 0; i < 4; i++) Ws[tid + i * 256] = Wv[tid + i * 256];

    agg_tile(Xs, x, r0, n, tid);
    __syncthreads();

    float4 acc[4];
    #pragma unroll
    for (int i = 0; i < 4; i++) acc[i] = make_float4(0.f, 0.f, 0.f, 0.f);

    #pragma unroll
    for (int k4 = 0; k4 < 16; k4++) {
        float4 xv[4];
        #pragma unroll
        for (int i = 0; i < 4; i++)
            xv[i] = *(const float4*)&Xs[(ty * 4 + i) * 68 + k4 * 4];
        #pragma unroll
        for (int j = 0; j < 4; j++) {
            float4 w = Ws[(k4 * 4 + j) * 16 + tx];
            #pragma unroll
            for (int i = 0; i < 4; i++) {
                float xs = (j == 0) ? xv[i].x : (j == 1) ? xv[i].y : (j == 2) ? xv[i].z : xv[i].w;
                acc[i].x = fmaf(xs, w.x, acc[i].x);
                acc[i].y = fmaf(xs, w.y, acc[i].y);
                acc[i].z = fmaf(xs, w.z, acc[i].z);
                acc[i].w = fmaf(xs, w.w, acc[i].w);
            }
        }
    }

    float4 b = ((const float4*)bias)[tx];
    #pragma unroll
    for (int i = 0; i < 4; i++) {
        int gr = r0 + ty * 4 + i;
        if (gr >= n) continue;
        float s = g_dis[gr];
        float4 a = acc[i];
        a.x = fmaxf(fmaf(s, a.x, b.x), 0.f);
        a.y = fmaxf(fmaf(s, a.y, b.y), 0.f);
        a.z = fmaxf(fmaf(s, a.z, b.z), 0.f);
        a.w = fmaxf(fmaf(s, a.w, b.w), 0.f);
        ((float4*)(out + (size_t)gr * DH))[tx] = a;
    }
}

// ---------------- fused classifier -------------------------------------------
// out = [ego | h1 | h2] @ W_cls + b_cls
//   ego = relu(x @ W_ego + b_ego)                 (in-register from x tile)
//   h2  = relu(dis*(agg(h1) @ Wc1) + b1)          (CSR-aggregate + in-register)
__global__ void k_cls(const float* __restrict__ x, const float* __restrict__ h1,
                      const float* __restrict__ Wego, const float* __restrict__ bego,
                      const float* __restrict__ Wc1,  const float* __restrict__ bc1,
                      const float* __restrict__ Wcls, const float* __restrict__ bcls,
                      float* __restrict__ out, int n)
{
    __shared__ float  Xs[64 * 68];     // 17408 B
    __shared__ float4 Wcs[192 * 10];   // 30720 B

    const int tx = threadIdx.x, ty = threadIdx.y;
    const int tid = ty * 16 + tx;
    const int r0 = blockIdx.x * 64;

    const float4* Wclsv = (const float4*)Wcls;
    #pragma unroll
    for (int i = tid; i < 1920; i += 256) Wcs[i] = Wclsv[i];

    float4 acc[4];
    #pragma unroll
    for (int i = 0; i < 4; i++) acc[i] = make_float4(0.f, 0.f, 0.f, 0.f);

    auto load_tile = [&](const float* S) {
        #pragma unroll
        for (int i = 0; i < 4; i++) {
            int idx = tid + i * 256;
            int rr = idx >> 4, cc = idx & 15;
            int gr = r0 + rr;
            float4 v = make_float4(0.f, 0.f, 0.f, 0.f);
            if (gr < n) v = ((const float4*)(S + (size_t)gr * DH))[cc];
            *(float4*)&Xs[rr * 68 + cc * 4] = v;
        }
    };

    // in-place 64x64 transform of Xs: Xs = relu(scale*(Xs@W)+b)
    auto transform = [&](const float* W, const float* bias, bool use_dis) {
        const float4* Wv = (const float4*)W;
        float4 t[4];
        #pragma unroll
        for (int i = 0; i < 4; i++) t[i] = make_float4(0.f, 0.f, 0.f, 0.f);
        #pragma unroll
        for (int k4 = 0; k4 < 16; k4++) {
            float4 xv[4];
            #pragma unroll
            for (int i = 0; i < 4; i++)
                xv[i] = *(const float4*)&Xs[(ty * 4 + i) * 68 + k4 * 4];
            #pragma unroll
            for (int j = 0; j < 4; j++) {
                float4 w = __ldg(&Wv[(k4 * 4 + j) * 16 + tx]);
                #pragma unroll
                for (int i = 0; i < 4; i++) {
                    float xs = (j == 0) ? xv[i].x : (j == 1) ? xv[i].y : (j == 2) ? xv[i].z : xv[i].w;
                    t[i].x = fmaf(xs, w.x, t[i].x);
                    t[i].y = fmaf(xs, w.y, t[i].y);
                    t[i].z = fmaf(xs, w.z, t[i].z);
                    t[i].w = fmaf(xs, w.w, t[i].w);
                }
            }
        }
        float4 b = __ldg(&((const float4*)bias)[tx]);
        __syncthreads();               // done reading old Xs
        #pragma unroll
        for (int i = 0; i < 4; i++) {
            int gr = r0 + ty * 4 + i;
            float s = 1.0f;
            if (use_dis) s = (gr < n) ? g_dis[gr] : 0.f;
            float4 a = t[i];
            a.x = fmaxf(fmaf(s, a.x, b.x), 0.f);
            a.y = fmaxf(fmaf(s, a.y, b.y), 0.f);
            a.z = fmaxf(fmaf(s, a.z, b.z), 0.f);
            a.w = fmaxf(fmaf(s, a.w, b.w), 0.f);
            *(float4*)&Xs[(ty * 4 + i) * 68 + tx * 4] = a;
        }
    };

    auto cls_accum = [&](int c) {
        if (tx < 10) {
            #pragma unroll
            for (int k4 = 0; k4 < 16; k4++) {
                float4 xv[4];
                #pragma unroll
                for (int i = 0; i < 4; i++)
                    xv[i] = *(const float4*)&Xs[(ty * 4 + i) * 68 + k4 * 4];
                #pragma unroll
                for (int j = 0; j < 4; j++) {
                    float4 w = Wcs[(c * 64 + k4 * 4 + j) * 10 + tx];
                    #pragma unroll
                    for (int i = 0; i < 4; i++) {
                        float xs = (j == 0) ? xv[i].x : (j == 1) ? xv[i].y : (j == 2) ? xv[i].z : xv[i].w;
                        acc[i].x = fmaf(xs, w.x, acc[i].x);
                        acc[i].y = fmaf(xs, w.y, acc[i].y);
                        acc[i].z = fmaf(xs, w.z, acc[i].z);
                        acc[i].w = fmaf(xs, w.w, acc[i].w);
                    }
                }
            }
        }
    };

    // phase 0: ego = relu(x @ Wego + bego)
    load_tile(x);
    __syncthreads();
    transform(Wego, bego, false);
    __syncthreads();
    cls_accum(0);
    __syncthreads();

    // phase 1: h1 (materialized)
    load_tile(h1);
    __syncthreads();
    cls_accum(1);
    __syncthreads();

    // phase 2: h2 = relu(dis*(agg(h1) @ Wc1) + b1), aggregated in-kernel
    agg_tile(Xs, h1, r0, n, tid);
    __syncthreads();
    transform(Wc1, bc1, true);
    __syncthreads();
    cls_accum(2);

    if (tx < 10) {
        float4 b = ((const float4*)bcls)[tx];
        #pragma unroll
        for (int i = 0; i < 4; i++) {
            int gr = r0 + ty * 4 + i;
            if (gr >= n) continue;
            float4 a = acc[i];
            a.x += b.x; a.y += b.y; a.z += b.z; a.w += b.w;
            *(float4*)(out + (size_t)gr * CC + tx * 4) = a;
        }
    }
}

// ---------------- launch -----------------------------------------------------
extern "C" void kernel_launch(void* const* d_in, const int* in_sizes, int n_in,
                              void* d_out, int out_size)
{
    const float* x      = (const float*)d_in[0];
    const void*  ei     = d_in[1];
    const float* W_ego  = (const float*)d_in[2];
    const float* b_ego  = (const float*)d_in[3];
    const float* W_conv = (const float*)d_in[4];   // [2, 64, 64]
    const float* b_conv = (const float*)d_in[5];   // [2, 64]
    const float* W_cls  = (const float*)d_in[6];   // [192, 40]
    const float* b_cls  = (const float*)d_in[7];   // [40]

    const int N = in_sizes[0] / DH;
    const int E = in_sizes[1] / 2;

    float* h1;
    cudaGetSymbolAddress((void**)&h1, g_h1);

    const int T = 256;
    const int NB = (N + T - 1) / T;            // <= 391
    const int EB = (E + T - 1) / T;
    const dim3 gb(16, 16);
    const int tile_blocks = (N + 63) / 64;

    // CSR build + normalization (4 kernels)
    k_init <<<NB, T>>>(ei, N);
    k_count<<<EB, T>>>(ei, E);
    k_scan <<<NB, T>>>(N);
    k_fill <<<EB, T>>>(ei, E);

    // hop 1: h1 = relu(dis*(agg(x)@Wc0)+b0)   (aggregation fused)
    k_hop1<<<tile_blocks, gb>>>(x, W_conv, b_conv, h1, N);

    // fused classifier: ego from x, h1 direct, h2 = agg(h1)+transform in-kernel
    k_cls<<<tile_blocks, gb>>>(x, h1,
                               W_ego, b_ego,
                               W_conv + DH * DH, b_conv + DH,
                               W_cls, b_cls, (float*)d_out, N);
}

// round 8
// speedup vs baseline: 1.0990x; 1.0990x over previous
#include <cuda_runtime.h>
#include <cstdint>

#define MAXN 100000
#define MAXE 1250000
#define DH   64
#define CC   40

// ---------------- device scratch (static; no runtime allocation) -------------
__device__ __align__(16) float g_dis[MAXN];
__device__ int   g_deg[MAXN];
__device__ int   g_rowptr[MAXN + 1];
__device__ int   g_cur[MAXN];
__device__ int   g_csr[MAXE];
__device__ volatile unsigned long long g_pack[512];   // lookback scan state
__device__ int   g_is64;
__device__ __align__(16) float g_y [(size_t)MAXN * DH];
__device__ __align__(16) float g_h1[(size_t)MAXN * DH];

// ---------------- helpers ----------------------------------------------------
__device__ __forceinline__ int edge_at(const void* ei, long long pos) {
    if (g_is64) return (int)((const long long*)ei)[pos];
    return ((const int*)ei)[pos];
}

// zero deg + scan state + int64/int32 detection, one kernel
__global__ void k_init(const void* ei, int n) {
    int i = blockIdx.x * blockDim.x + threadIdx.x;
    if (i < n) g_deg[i] = 0;
    if (i < 512) g_pack[i] = 0ull;
    if (i == 0) {
        const long long* p = (const long long*)ei;
        int ok = 1;
        #pragma unroll
        for (int k = 0; k < 8; k++) {
            long long v = p[k];
            if (v < 0 || v >= (long long)n) ok = 0;
        }
        g_is64 = ok;
    }
}

__global__ void k_count(const void* ei, int E) {
    int e = blockIdx.x * blockDim.x + threadIdx.x;
    if (e < E) atomicAdd(&g_deg[edge_at(ei, (long long)E + e)], 1);
}

// ---- single-pass exclusive scan (decoupled lookback) -> rowptr/cur/dis ------
#define FLAG_AGG (1ull << 62)
#define FLAG_PRE (2ull << 62)

__global__ void k_scan(int n) {
    __shared__ int s[256];
    __shared__ int s_prefix;
    const int b = blockIdx.x;
    const int t = threadIdx.x;
    const int i = b * 256 + t;
    const int v = (i < n) ? g_deg[i] : 0;

    s[t] = v;
    __syncthreads();
    #pragma unroll
    for (int off = 1; off < 256; off <<= 1) {
        int add = (t >= off) ? s[t - off] : 0;
        __syncthreads();
        s[t] += add;
        __syncthreads();
    }

    if (t == 0) {
        int total = s[255];
        if (b == 0) {
            g_pack[0] = FLAG_PRE | (unsigned long long)(unsigned)total;
            s_prefix = 0;
        } else {
            g_pack[b] = FLAG_AGG | (unsigned long long)(unsigned)total;
            int prefix = 0;
            int j = b - 1;
            while (true) {
                unsigned long long p;
                while ((p = g_pack[j]) == 0ull) { /* spin */ }
                int val = (int)(p & 0xFFFFFFFFull);
                prefix += val;
                if (p & FLAG_PRE) break;
                j--;
            }
            g_pack[b] = FLAG_PRE | (unsigned long long)(unsigned)(prefix + total);
            s_prefix = prefix;
        }
    }
    __syncthreads();

    if (i < n) {
        int excl = s_prefix + s[t] - v;
        g_rowptr[i] = excl;
        g_cur[i]    = excl;
        g_dis[i]    = rsqrtf((float)(v + 1));     // +1 = self-loop
        if (i == n - 1) g_rowptr[n] = excl + v;
    }
}

__global__ void k_fill(const void* ei, int E) {
    int e = blockIdx.x * blockDim.x + threadIdx.x;
    if (e < E) {
        int r = edge_at(ei, (long long)e);
        int c = edge_at(ei, (long long)E + e);
        int pos = atomicAdd(&g_cur[c], 1);
        g_csr[pos] = r;
    }
}

// -------- gather-first aggregation: y_i = dis_i*src_i + sum_nbr dis_r*src_r ---
// 16 lanes per node, float4 per lane; 2 independent nodes per warp (MLP x2).
__global__ void k_agg(const float* __restrict__ src, float* __restrict__ y, int n)
{
    const int gid  = blockIdx.x * blockDim.x + threadIdx.x;
    const int node = gid >> 4;
    const int j    = threadIdx.x & 15;
    if (node >= n) return;

    const float4* H = (const float4*)src;
    const float   dw = g_dis[node];
    float4 v0 = H[(size_t)node * 16 + j];
    float4 acc = make_float4(dw * v0.x, dw * v0.y, dw * v0.z, dw * v0.w);

    int p   = g_rowptr[node];
    int end = g_rowptr[node + 1];
    for (; p + 3 < end; p += 4) {
        int s0 = __ldg(&g_csr[p]);
        int s1 = __ldg(&g_csr[p + 1]);
        int s2 = __ldg(&g_csr[p + 2]);
        int s3 = __ldg(&g_csr[p + 3]);
        float d0 = __ldg(&g_dis[s0]);
        float d1 = __ldg(&g_dis[s1]);
        float d2 = __ldg(&g_dis[s2]);
        float d3 = __ldg(&g_dis[s3]);
        float4 a = H[(size_t)s0 * 16 + j];
        float4 b = H[(size_t)s1 * 16 + j];
        float4 c = H[(size_t)s2 * 16 + j];
        float4 d = H[(size_t)s3 * 16 + j];
        acc.x = fmaf(d0, a.x, fmaf(d1, b.x, fmaf(d2, c.x, fmaf(d3, d.x, acc.x))));
        acc.y = fmaf(d0, a.y, fmaf(d1, b.y, fmaf(d2, c.y, fmaf(d3, d.y, acc.y))));
        acc.z = fmaf(d0, a.z, fmaf(d1, b.z, fmaf(d2, c.z, fmaf(d3, d.z, acc.z))));
        acc.w = fmaf(d0, a.w, fmaf(d1, b.w, fmaf(d2, c.w, fmaf(d3, d.w, acc.w))));
    }
    for (; p < end; p++) {
        int s0 = __ldg(&g_csr[p]);
        float d0 = __ldg(&g_dis[s0]);
        float4 a = H[(size_t)s0 * 16 + j];
        acc.x = fmaf(d0, a.x, acc.x);
        acc.y = fmaf(d0, a.y, acc.y);
        acc.z = fmaf(d0, a.z, acc.z);
        acc.w = fmaf(d0, a.w, acc.w);
    }
    ((float4*)y)[(size_t)node * 16 + j] = acc;
}

// ------------- GEMM+finish: h = relu(dis_i * (y @ W) + b) --------------------
__global__ void k_gemm_h(const float* __restrict__ Y, const float* __restrict__ W,
                         const float* __restrict__ bias, float* __restrict__ out, int n)
{
    __shared__ float  Xs[64 * 64];
    __shared__ float4 Ws[64 * 16];

    const int tx = threadIdx.x, ty = threadIdx.y;
    const int tid = ty * 16 + tx;

    const float4* Wv = (const float4*)W;
    #pragma unroll
    for (int i = 0; i < 4; i++) Ws[tid + i * 256] = Wv[tid + i * 256];

    const int r0 = blockIdx.x * 64;
    #pragma unroll
    for (int i = 0; i < 4; i++) {
        int idx = tid + i * 256;
        int rr = idx >> 4, cc = idx & 15;
        int gr = r0 + rr;
        float4 v = make_float4(0.f, 0.f, 0.f, 0.f);
        if (gr < n) v = ((const float4*)(Y + (size_t)gr * DH))[cc];
        *(float4*)&Xs[rr * 64 + cc * 4] = v;
    }
    __syncthreads();

    float4 acc[4];
    #pragma unroll
    for (int i = 0; i < 4; i++) acc[i] = make_float4(0.f, 0.f, 0.f, 0.f);

    #pragma unroll
    for (int k4 = 0; k4 < 16; k4++) {
        float4 xv[4];
        #pragma unroll
        for (int i = 0; i < 4; i++)
            xv[i] = *(const float4*)&Xs[(ty * 4 + i) * 64 + k4 * 4];
        #pragma unroll
        for (int j = 0; j < 4; j++) {
            float4 w = Ws[(k4 * 4 + j) * 16 + tx];
            #pragma unroll
            for (int i = 0; i < 4; i++) {
                float xs = (j == 0) ? xv[i].x : (j == 1) ? xv[i].y : (j == 2) ? xv[i].z : xv[i].w;
                acc[i].x = fmaf(xs, w.x, acc[i].x);
                acc[i].y = fmaf(xs, w.y, acc[i].y);
                acc[i].z = fmaf(xs, w.z, acc[i].z);
                acc[i].w = fmaf(xs, w.w, acc[i].w);
            }
        }
    }

    float4 b = ((const float4*)bias)[tx];
    #pragma unroll
    for (int i = 0; i < 4; i++) {
        int gr = r0 + ty * 4 + i;
        if (gr >= n) continue;
        float s = g_dis[gr];
        float4 a = acc[i];
        a.x = fmaxf(fmaf(s, a.x, b.x), 0.f);
        a.y = fmaxf(fmaf(s, a.y, b.y), 0.f);
        a.z = fmaxf(fmaf(s, a.z, b.z), 0.f);
        a.w = fmaxf(fmaf(s, a.w, b.w), 0.f);
        ((float4*)(out + (size_t)gr * DH))[tx] = a;
    }
}

// ---------------- fused classifier -------------------------------------------
// out = [ego | h1 | h2] @ W_cls + b_cls
//   ego = relu(x @ W_ego + b_ego)       (in-register from x tile)
//   h2  = relu(dis*(y2 @ Wc1) + b1)     (in-register from pre-aggregated y2)
__global__ void k_cls(const float* __restrict__ x, const float* __restrict__ h1,
                      const float* __restrict__ y2,
                      const float* __restrict__ Wego, const float* __restrict__ bego,
                      const float* __restrict__ Wc1,  const float* __restrict__ bc1,
                      const float* __restrict__ Wcls, const float* __restrict__ bcls,
                      float* __restrict__ out, int n)
{
    __shared__ float  Xs[64 * 68];     // 17408 B
    __shared__ float4 Wcs[192 * 10];   // 30720 B

    const int tx = threadIdx.x, ty = threadIdx.y;
    const int tid = ty * 16 + tx;
    const int r0 = blockIdx.x * 64;

    const float4* Wclsv = (const float4*)Wcls;
    #pragma unroll
    for (int i = tid; i < 1920; i += 256) Wcs[i] = Wclsv[i];

    float4 acc[4];
    #pragma unroll
    for (int i = 0; i < 4; i++) acc[i] = make_float4(0.f, 0.f, 0.f, 0.f);

    auto load_tile = [&](const float* S) {
        #pragma unroll
        for (int i = 0; i < 4; i++) {
            int idx = tid + i * 256;
            int rr = idx >> 4, cc = idx & 15;
            int gr = r0 + rr;
            float4 v = make_float4(0.f, 0.f, 0.f, 0.f);
            if (gr < n) v = ((const float4*)(S + (size_t)gr * DH))[cc];
            *(float4*)&Xs[rr * 68 + cc * 4] = v;
        }
    };

    // in-place 64x64 transform of Xs: Xs = relu(scale*(Xs@W)+b)
    auto transform = [&](const float* W, const float* bias, bool use_dis) {
        const float4* Wv = (const float4*)W;
        float4 t[4];
        #pragma unroll
        for (int i = 0; i < 4; i++) t[i] = make_float4(0.f, 0.f, 0.f, 0.f);
        #pragma unroll
        for (int k4 = 0; k4 < 16; k4++) {
            float4 xv[4];
            #pragma unroll
            for (int i = 0; i < 4; i++)
                xv[i] = *(const float4*)&Xs[(ty * 4 + i) * 68 + k4 * 4];
            #pragma unroll
            for (int j = 0; j < 4; j++) {
                float4 w = __ldg(&Wv[(k4 * 4 + j) * 16 + tx]);
                #pragma unroll
                for (int i = 0; i < 4; i++) {
                    float xs = (j == 0) ? xv[i].x : (j == 1) ? xv[i].y : (j == 2) ? xv[i].z : xv[i].w;
                    t[i].x = fmaf(xs, w.x, t[i].x);
                    t[i].y = fmaf(xs, w.y, t[i].y);
                    t[i].z = fmaf(xs, w.z, t[i].z);
                    t[i].w = fmaf(xs, w.w, t[i].w);
                }
            }
        }
        float4 b = __ldg(&((const float4*)bias)[tx]);
        __syncthreads();               // done reading old Xs
        #pragma unroll
        for (int i = 0; i < 4; i++) {
            int gr = r0 + ty * 4 + i;
            float s = 1.0f;
            if (use_dis) s = (gr < n) ? g_dis[gr] : 0.f;
            float4 a = t[i];
            a.x = fmaxf(fmaf(s, a.x, b.x), 0.f);
            a.y = fmaxf(fmaf(s, a.y, b.y), 0.f);
            a.z = fmaxf(fmaf(s, a.z, b.z), 0.f);
            a.w = fmaxf(fmaf(s, a.w, b.w), 0.f);
            *(float4*)&Xs[(ty * 4 + i) * 68 + tx * 4] = a;
        }
    };

    auto cls_accum = [&](int c) {
        if (tx < 10) {
            #pragma unroll
            for (int k4 = 0; k4 < 16; k4++) {
                float4 xv[4];
                #pragma unroll
                for (int i = 0; i < 4; i++)
                    xv[i] = *(const float4*)&Xs[(ty * 4 + i) * 68 + k4 * 4];
                #pragma unroll
                for (int j = 0; j < 4; j++) {
                    float4 w = Wcs[(c * 64 + k4 * 4 + j) * 10 + tx];
                    #pragma unroll
                    for (int i = 0; i < 4; i++) {
                        float xs = (j == 0) ? xv[i].x : (j == 1) ? xv[i].y : (j == 2) ? xv[i].z : xv[i].w;
                        acc[i].x = fmaf(xs, w.x, acc[i].x);
                        acc[i].y = fmaf(xs, w.y, acc[i].y);
                        acc[i].z = fmaf(xs, w.z, acc[i].z);
                        acc[i].w = fmaf(xs, w.w, acc[i].w);
                    }
                }
            }
        }
    };

    // phase 0: ego = relu(x @ Wego + bego)
    load_tile(x);
    __syncthreads();
    transform(Wego, bego, false);
    __syncthreads();
    cls_accum(0);
    __syncthreads();

    // phase 1: h1 (materialized)
    load_tile(h1);
    __syncthreads();
    cls_accum(1);
    __syncthreads();

    // phase 2: h2 = relu(dis*(y2 @ Wc1) + b1)
    load_tile(y2);
    __syncthreads();
    transform(Wc1, bc1, true);
    __syncthreads();
    cls_accum(2);

    if (tx < 10) {
        float4 b = ((const float4*)bcls)[tx];
        #pragma unroll
        for (int i = 0; i < 4; i++) {
            int gr = r0 + ty * 4 + i;
            if (gr >= n) continue;
            float4 a = acc[i];
            a.x += b.x; a.y += b.y; a.z += b.z; a.w += b.w;
            *(float4*)(out + (size_t)gr * CC + tx * 4) = a;
        }
    }
}

// ---------------- launch -----------------------------------------------------
extern "C" void kernel_launch(void* const* d_in, const int* in_sizes, int n_in,
                              void* d_out, int out_size)
{
    const float* x      = (const float*)d_in[0];
    const void*  ei     = d_in[1];
    const float* W_ego  = (const float*)d_in[2];
    const float* b_ego  = (const float*)d_in[3];
    const float* W_conv = (const float*)d_in[4];   // [2, 64, 64]
    const float* b_conv = (const float*)d_in[5];   // [2, 64]
    const float* W_cls  = (const float*)d_in[6];   // [192, 40]
    const float* b_cls  = (const float*)d_in[7];   // [40]

    const int N = in_sizes[0] / DH;
    const int E = in_sizes[1] / 2;

    float *y, *h1;
    cudaGetSymbolAddress((void**)&y,  g_y);
    cudaGetSymbolAddress((void**)&h1, g_h1);

    const int T = 256;
    const int NB = (N + T - 1) / T;
    const int EB = (E + T - 1) / T;
    const dim3 gb(16, 16);
    const int tile_blocks = (N + 63) / 64;
    const int agg_blocks = (int)(((long long)N * 16 + T - 1) / T);

    // CSR build + normalization
    k_init <<<NB, T>>>(ei, N);
    k_count<<<EB, T>>>(ei, E);
    k_scan <<<NB, T>>>(N);
    k_fill <<<EB, T>>>(ei, E);

    // hop 1: y1 = gather(dis*x);  h1 = relu(dis*(y1@Wc0) + b0)
    k_agg   <<<agg_blocks, T>>>(x, y, N);
    k_gemm_h<<<tile_blocks, gb>>>(y, W_conv, b_conv, h1, N);

    // hop 2: y2 = gather(dis*h1)   (h2 virtualized into k_cls)
    k_agg   <<<agg_blocks, T>>>(h1, y, N);

    // fused classifier
    k_cls<<<tile_blocks, gb>>>(x, h1, y,
                               W_ego, b_ego,
                               W_conv + DH * DH, b_conv + DH,
                               W_cls, b_cls, (float*)d_out, N);
}